// round 14
// baseline (speedup 1.0000x reference)
#include <cuda_runtime.h>
#include <cuda_bf16.h>
#include <cuda_fp16.h>
#include <cstdint>

#define NNODES 100000
#define NEDGES 1600000
#define FEAT   128
#define NCH    4

// -------- scratch (static device globals; allocation-free per harness rules) ----
__device__ __align__(16) __half g_self [NNODES * FEAT];  // layer1 self (fp16)
__device__ __align__(16) __half g_msg  [NNODES * FEAT];  // layer1 msg  (fp16)
__device__ __align__(16) __half g_hh   [NNODES * FEAT];  // hidden h    (fp16)
__device__ __align__(16) __half g_msg2 [NNODES * FEAT];  // layer2 msg  (fp16)
__device__ __align__(16) __half g_xh   [NNODES * FEAT];  // x rounded to fp16
__device__ int g_deg[NNODES];
__device__ int g_row_start[NNODES + 1];
__device__ int g_csr[NEDGES];
// fp16 split weights, pre-transposed to [layer][n(0..255)][k(0..127)]
__device__ __align__(16) __half g_B0[2 * 256 * 128];   // hi
__device__ __align__(16) __half g_B1[2 * 256 * 128];   // lo (residual)

// ================================ helpers =======================================
__device__ __forceinline__ uint32_t sm_u32(const void* p) {
    uint32_t a;
    asm("{ .reg .u64 t; cvta.to.shared.u64 t, %1; cvt.u32.u64 %0, t; }"
        : "=r"(a) : "l"(p));
    return a;
}
__device__ __forceinline__ void ldsm_x4(uint32_t* r, uint32_t addr) {
    asm volatile("ldmatrix.sync.aligned.m8n8.x4.shared.b16 {%0,%1,%2,%3}, [%4];"
                 : "=r"(r[0]), "=r"(r[1]), "=r"(r[2]), "=r"(r[3]) : "r"(addr));
}
__device__ __forceinline__ void mma16816(float* c, const uint32_t* a,
                                         uint32_t b0, uint32_t b1) {
    asm volatile("mma.sync.aligned.m16n8k16.row.col.f32.f16.f16.f32 "
                 "{%0,%1,%2,%3}, {%4,%5,%6,%7}, {%8,%9}, {%0,%1,%2,%3};"
                 : "+f"(c[0]), "+f"(c[1]), "+f"(c[2]), "+f"(c[3])
                 : "r"(a[0]), "r"(a[1]), "r"(a[2]), "r"(a[3]), "r"(b0), "r"(b1));
}
__device__ __forceinline__ void cp16(uint32_t saddr, const void* g, int src_sz) {
    asm volatile("cp.async.cg.shared.global [%0], [%1], 16, %2;"
                 :: "r"(saddr), "l"(g), "r"(src_sz) : "memory");
}
__device__ __forceinline__ void cp_commit() {
    asm volatile("cp.async.commit_group;" ::: "memory");
}
// ---- L2 eviction-priority via createpolicy + cache_hint ----
__device__ __forceinline__ uint64_t pol_evict_last() {
    uint64_t p;
    asm("createpolicy.fractional.L2::evict_last.b64 %0, 1.0;" : "=l"(p));
    return p;
}
__device__ __forceinline__ uint64_t pol_evict_first() {
    uint64_t p;
    asm("createpolicy.fractional.L2::evict_first.b64 %0, 1.0;" : "=l"(p));
    return p;
}
__device__ __forceinline__ uint4 ldg_hint_u4(const void* p, uint64_t pol) {
    uint4 v;
    asm volatile("ld.global.nc.L2::cache_hint.v4.u32 {%0,%1,%2,%3}, [%4], %5;"
                 : "=r"(v.x), "=r"(v.y), "=r"(v.z), "=r"(v.w) : "l"(p), "l"(pol));
    return v;
}
__device__ __forceinline__ void stg_hint_f4(void* p, float4 v, uint64_t pol) {
    asm volatile("st.global.L2::cache_hint.v4.f32 [%0], {%1,%2,%3,%4}, %5;"
                 :: "l"(p), "f"(v.x), "f"(v.y), "f"(v.z), "f"(v.w), "l"(pol)
                 : "memory");
}
__device__ __forceinline__ void stg_hint_u32(void* p, uint32_t v, uint64_t pol) {
    asm volatile("st.global.L2::cache_hint.u32 [%0], %1, %2;"
                 :: "l"(p), "r"(v), "l"(pol) : "memory");
}

// ============================= prep kernels (once) ==============================
__global__ void wprep_kernel(const float* __restrict__ W_in,
                             const float* __restrict__ W_out) {
    int idx = blockIdx.x * blockDim.x + threadIdx.x;
    if (idx >= 2 * 256 * 128) return;
    int layer = idx >> 15;
    int n = (idx >> 7) & 255;
    int k = idx & 127;
    const float* W = (layer ? W_out : W_in) + ((n >= 128) ? 128 * 128 : 0);
    float w = W[k * 128 + (n & 127)];
    __half w0 = __float2half_rn(w);
    __half w1 = __float2half_rn(w - __half2float(w0));
    g_B0[idx] = w0;
    g_B1[idx] = w1;
}
__global__ void xh_kernel(const float* __restrict__ x, int n4) {
    int i = blockIdx.x * blockDim.x + threadIdx.x;
    if (i >= n4) return;
    float4 v = ((const float4*)x)[i];
    __half2 t0 = __floats2half2_rn(v.x, v.y);
    __half2 t1 = __floats2half2_rn(v.z, v.w);
    uint2 p = make_uint2(*(uint32_t*)&t0, *(uint32_t*)&t1);
    ((uint2*)g_xh)[i] = p;
}

// =============================== CSR build ======================================
__global__ void zero_int_kernel(int* __restrict__ a, int n) {
    int i = blockIdx.x * blockDim.x + threadIdx.x;
    if (i < n) a[i] = 0;
}
__global__ void deg_kernel(const int* __restrict__ dst, int E) {
    int e = blockIdx.x * blockDim.x + threadIdx.x;
    if (e < E) atomicAdd(&g_deg[dst[e]], 1);
}
__global__ void scan_kernel(int n) {
    __shared__ int part[1024];
    const int T = 1024;
    int tid = threadIdx.x;
    int chunk = (n + T - 1) / T;
    int b = tid * chunk, e = min(b + chunk, n);
    int s = 0;
    for (int i = b; i < e; ++i) s += g_deg[i];
    part[tid] = s;
    __syncthreads();
    if (tid == 0) {
        int run = 0;
        for (int i = 0; i < T; ++i) { int t = part[i]; part[i] = run; run += t; }
    }
    __syncthreads();
    int run = part[tid];
    for (int i = b; i < e; ++i) { g_row_start[i] = run; run += g_deg[i]; }
    if (e == n) g_row_start[n] = run;
}
__global__ void fill_kernel(const int* __restrict__ src,
                            const int* __restrict__ dst, int E) {
    int e = blockIdx.x * blockDim.x + threadIdx.x;
    if (e < E) {
        int d = dst[e];
        int slot = g_row_start[d] + atomicSub(&g_deg[d], 1) - 1;
        g_csr[slot] = src[e];
    }
}

// ====== persistent mma.sync dual GEMM (N=256, layer 1), cp.async pipelined ======
#define GT 512
#define SM_A0  0                 // 32 KB
#define SM_A1  32768             // 32 KB
#define SM_BHI 65536             // 64 KB (256 rows)
#define SM_BLO 131072            // 32 KB (self half only)
#define SMEM_TOTAL_GEMM 163840

__device__ __forceinline__ void prefetch_A(uint32_t sb, int buf,
                                           const __half* __restrict__ feath,
                                           int row0, int nrows) {
    const uint32_t base = sb + (buf ? SM_A1 : SM_A0);
    int idx = threadIdx.x;
    #pragma unroll
    for (int j = 0; j < 4; ++j, idx += GT) {
        int r = idx >> 4, ch = idx & 15;
        int row = row0 + r;
        uint32_t off = r * 256 + ((ch ^ (r & 7)) << 4);
        cp16(base + off, feath + (size_t)row * 128 + ch * 8,
             (row < nrows) ? 16 : 0);
    }
}

__global__ __launch_bounds__(GT, 1)
void mma_gemm_kernel(const __half* __restrict__ feath,
                     const __half* __restrict__ Bg0,
                     const __half* __restrict__ Bg1,
                     __half* __restrict__ out_selfh,
                     __half* __restrict__ out_msg,
                     int row_base, int nrows, int ntiles)
{
    extern __shared__ char smc[];
    const int tid = threadIdx.x;
    const uint32_t sb = sm_u32(smc);

    {
        int idx = tid;
        #pragma unroll
        for (int j = 0; j < 8; ++j, idx += GT) {
            int n = idx >> 4, ch = idx & 15;
            uint32_t off = n * 256 + ((ch ^ (n & 7)) << 4);
            cp16(sb + SM_BHI + off, Bg0 + n * 128 + ch * 8, 16);
        }
        idx = tid;
        #pragma unroll
        for (int j = 0; j < 4; ++j, idx += GT) {
            int n = idx >> 4, ch = idx & 15;
            uint32_t off = n * 256 + ((ch ^ (n & 7)) << 4);
            cp16(sb + SM_BLO + off, Bg1 + n * 128 + ch * 8, 16);
        }
    }
    int t = blockIdx.x;
    const int stride = gridDim.x;
    if (t < ntiles) prefetch_A(sb, 0, feath, row_base + t * 128, nrows);
    cp_commit();

    const int wid = tid >> 5, lane = tid & 31;
    const int mw = wid & 3;
    const int nw = wid >> 2;
    const bool self_half = (nw < 2);
    const int s3 = lane & 7, sel = lane >> 3;
    const int g = lane >> 2, tq = lane & 3;
    const int colhalf = (nw & 1) * 64;
    const uint64_t pL = pol_evict_last();

    int cur = 0;
    for (; t < ntiles; t += stride, cur ^= 1) {
        const int row0 = row_base + t * 128;
        const int nt_tile = t + stride;
        const bool has_next = (nt_tile < ntiles);

        if (has_next) {
            prefetch_A(sb, cur ^ 1, feath, row_base + nt_tile * 128, nrows);
            cp_commit();
            asm volatile("cp.async.wait_group 1;" ::: "memory");
        } else {
            asm volatile("cp.async.wait_group 0;" ::: "memory");
        }
        __syncthreads();

        const uint32_t abase = sb + (cur ? SM_A1 : SM_A0);

        float acc[2][8][4];
        #pragma unroll
        for (int a = 0; a < 2; ++a)
            #pragma unroll
            for (int b = 0; b < 8; ++b)
                #pragma unroll
                for (int c = 0; c < 4; ++c) acc[a][b][c] = 0.f;

        #pragma unroll
        for (int ks = 0; ks < 8; ++ks) {
            uint32_t ahi[2][4];
            #pragma unroll
            for (int mt = 0; mt < 2; ++mt) {
                int r = mw * 32 + mt * 16 + s3 + ((sel & 1) << 3);
                int ch = 2 * ks + (sel >> 1);
                uint32_t off = r * 256 + ((ch ^ (r & 7)) << 4);
                ldsm_x4(ahi[mt], abase + off);
            }
            #pragma unroll
            for (int jp = 0; jp < 4; ++jp) {
                int r = nw * 64 + jp * 16 + s3 + ((sel >> 1) << 3);
                int ch = 2 * ks + (sel & 1);
                uint32_t off = r * 256 + ((ch ^ (r & 7)) << 4);
                uint32_t bhi[4], blo[4];
                ldsm_x4(bhi, sb + SM_BHI + off);
                if (self_half) ldsm_x4(blo, sb + SM_BLO + off);
                #pragma unroll
                for (int tt = 0; tt < 2; ++tt) {
                    int nt = jp * 2 + tt;
                    #pragma unroll
                    for (int mt = 0; mt < 2; ++mt) {
                        mma16816(acc[mt][nt], ahi[mt], bhi[2*tt], bhi[2*tt+1]);
                        if (self_half)
                            mma16816(acc[mt][nt], ahi[mt], blo[2*tt], blo[2*tt+1]);
                    }
                }
            }
        }

        // ---- epilogue: both halves fp16, pinned (layer-1 agg read set)
        __half* dst = self_half ? out_selfh : out_msg;
        #pragma unroll
        for (int mt = 0; mt < 2; ++mt) {
            int rr = row0 + mw * 32 + mt * 16 + g;
            #pragma unroll
            for (int nt = 0; nt < 8; ++nt) {
                int col = colhalf + nt * 8 + 2 * tq;
                if (rr < nrows) {
                    __half2 h = __floats2half2_rn(acc[mt][nt][0], acc[mt][nt][1]);
                    stg_hint_u32(dst + (size_t)rr * 128 + col, *(uint32_t*)&h, pL);
                }
                if (rr + 8 < nrows) {
                    __half2 h = __floats2half2_rn(acc[mt][nt][2], acc[mt][nt][3]);
                    stg_hint_u32(dst + (size_t)(rr + 8) * 128 + col, *(uint32_t*)&h, pL);
                }
            }
        }
        __syncthreads();
    }
}

// ====== persistent mma.sync GEMM, N=128 (layer-2 halves) ========================
// outh != null : write fp16 (msg2 pass, 1 chain, Bg1 == null)
// outh == null : RMW fp32  (self pass, 2 chains): outf[r] += acc
#define SMN_BHI 65536            // 32 KB (128 rows)
#define SMN_BLO 98304            // 32 KB
#define SMEM_TOTAL_N128 131072

__global__ __launch_bounds__(GT, 1)
void mma_gemm_n128_kernel(const __half* __restrict__ feath,
                          const __half* __restrict__ Bg0,
                          const __half* __restrict__ Bg1,
                          float* __restrict__ outf,
                          __half* __restrict__ outh,
                          int row_base, int nrows, int ntiles)
{
    extern __shared__ char smc[];
    const int tid = threadIdx.x;
    const uint32_t sb = sm_u32(smc);
    const bool two_chain = (Bg1 != nullptr);

    {
        int idx = tid;
        #pragma unroll
        for (int j = 0; j < 4; ++j, idx += GT) {  // BHI: 128 rows x 16 chunks
            int n = idx >> 4, ch = idx & 15;
            uint32_t off = n * 256 + ((ch ^ (n & 7)) << 4);
            cp16(sb + SMN_BHI + off, Bg0 + n * 128 + ch * 8, 16);
        }
        if (two_chain) {
            idx = tid;
            #pragma unroll
            for (int j = 0; j < 4; ++j, idx += GT) {
                int n = idx >> 4, ch = idx & 15;
                uint32_t off = n * 256 + ((ch ^ (n & 7)) << 4);
                cp16(sb + SMN_BLO + off, Bg1 + n * 128 + ch * 8, 16);
            }
        }
    }
    int t = blockIdx.x;
    const int stride = gridDim.x;
    if (t < ntiles) prefetch_A(sb, 0, feath, row_base + t * 128, nrows);
    cp_commit();

    const int wid = tid >> 5, lane = tid & 31;
    const int mw = wid & 3;
    const int nw = wid >> 2;          // 4 blocks of 32 cols
    const int s3 = lane & 7, sel = lane >> 3;
    const int g = lane >> 2, tq = lane & 3;
    const uint64_t pL = pol_evict_last();

    int cur = 0;
    for (; t < ntiles; t += stride, cur ^= 1) {
        const int row0 = row_base + t * 128;
        const int nt_tile = t + stride;
        const bool has_next = (nt_tile < ntiles);

        if (has_next) {
            prefetch_A(sb, cur ^ 1, feath, row_base + nt_tile * 128, nrows);
            cp_commit();
            asm volatile("cp.async.wait_group 1;" ::: "memory");
        } else {
            asm volatile("cp.async.wait_group 0;" ::: "memory");
        }
        __syncthreads();

        const uint32_t abase = sb + (cur ? SM_A1 : SM_A0);

        float acc[2][4][4];
        #pragma unroll
        for (int a = 0; a < 2; ++a)
            #pragma unroll
            for (int b = 0; b < 4; ++b)
                #pragma unroll
                for (int c = 0; c < 4; ++c) acc[a][b][c] = 0.f;

        #pragma unroll
        for (int ks = 0; ks < 8; ++ks) {
            uint32_t ahi[2][4];
            #pragma unroll
            for (int mt = 0; mt < 2; ++mt) {
                int r = mw * 32 + mt * 16 + s3 + ((sel & 1) << 3);
                int ch = 2 * ks + (sel >> 1);
                uint32_t off = r * 256 + ((ch ^ (r & 7)) << 4);
                ldsm_x4(ahi[mt], abase + off);
            }
            #pragma unroll
            for (int jp = 0; jp < 2; ++jp) {
                int r = nw * 32 + jp * 16 + s3 + ((sel >> 1) << 3);
                int ch = 2 * ks + (sel & 1);
                uint32_t off = r * 256 + ((ch ^ (r & 7)) << 4);
                uint32_t bhi[4], blo[4];
                ldsm_x4(bhi, sb + SMN_BHI + off);
                if (two_chain) ldsm_x4(blo, sb + SMN_BLO + off);
                #pragma unroll
                for (int tt = 0; tt < 2; ++tt) {
                    int nt = jp * 2 + tt;
                    #pragma unroll
                    for (int mt = 0; mt < 2; ++mt) {
                        mma16816(acc[mt][nt], ahi[mt], bhi[2*tt], bhi[2*tt+1]);
                        if (two_chain)
                            mma16816(acc[mt][nt], ahi[mt], blo[2*tt], blo[2*tt+1]);
                    }
                }
            }
        }

        // ---- epilogue
        #pragma unroll
        for (int mt = 0; mt < 2; ++mt) {
            int rr = row0 + mw * 32 + mt * 16 + g;
            #pragma unroll
            for (int nt = 0; nt < 4; ++nt) {
                int col = nw * 32 + nt * 8 + 2 * tq;
                if (outh) {
                    if (rr < nrows) {
                        __half2 h = __floats2half2_rn(acc[mt][nt][0], acc[mt][nt][1]);
                        stg_hint_u32(outh + (size_t)rr * 128 + col, *(uint32_t*)&h, pL);
                    }
                    if (rr + 8 < nrows) {
                        __half2 h = __floats2half2_rn(acc[mt][nt][2], acc[mt][nt][3]);
                        stg_hint_u32(outh + (size_t)(rr + 8) * 128 + col, *(uint32_t*)&h, pL);
                    }
                } else {
                    if (rr < nrows) {
                        float2* p = (float2*)(outf + (size_t)rr * 128 + col);
                        float2 o = *p;
                        o.x += acc[mt][nt][0]; o.y += acc[mt][nt][1];
                        *p = o;
                    }
                    if (rr + 8 < nrows) {
                        float2* p = (float2*)(outf + (size_t)(rr + 8) * 128 + col);
                        float2 o = *p;
                        o.x += acc[mt][nt][2]; o.y += acc[mt][nt][3];
                        *p = o;
                    }
                }
            }
        }
        __syncthreads();
    }
}

// ------- CSR gather-mean: 2 dst-nodes per warp, 16 lanes x LDG.128 per row ------
// selfh: fp16 self (layer1) | null. Both null -> mean-only (writes outf).
__global__ void agg_csr_kernel(const __half* __restrict__ msg,
                               const __half* __restrict__ selfh,
                               float* __restrict__ outf,
                               __half* __restrict__ outh,
                               int node_base, int node_end, int relu)
{
    const int gwarp = (blockIdx.x * blockDim.x + threadIdx.x) >> 5;
    const int lane = threadIdx.x & 31;
    const int hw = lane >> 4;
    const int l16 = lane & 15;
    const int w = node_base + gwarp * 2 + hw;
    if (w >= node_end) return;

    const uint64_t pL = pol_evict_last();
    const uint64_t pF = pol_evict_first();

    const int beg = __ldg(&g_row_start[w]);
    const int end = __ldg(&g_row_start[w + 1]);

    float acc[8];
    #pragma unroll
    for (int j = 0; j < 8; ++j) acc[j] = 0.f;

    int e = beg;
    for (; e + 8 <= end; e += 8) {
        int s[8];
        #pragma unroll
        for (int j = 0; j < 8; ++j) s[j] = __ldg(&g_csr[e + j]);
        uint4 u[8];
        #pragma unroll
        for (int j = 0; j < 8; ++j)
            u[j] = ldg_hint_u4(msg + (size_t)s[j] * 128 + l16 * 8, pL);
        #pragma unroll
        for (int j = 0; j < 8; ++j) {
            float2 f;
            f = __half22float2(*(__half2*)&u[j].x); acc[0] += f.x; acc[1] += f.y;
            f = __half22float2(*(__half2*)&u[j].y); acc[2] += f.x; acc[3] += f.y;
            f = __half22float2(*(__half2*)&u[j].z); acc[4] += f.x; acc[5] += f.y;
            f = __half22float2(*(__half2*)&u[j].w); acc[6] += f.x; acc[7] += f.y;
        }
    }
    for (; e + 2 <= end; e += 2) {
        int s0 = __ldg(&g_csr[e]), s1 = __ldg(&g_csr[e + 1]);
        uint4 u0 = ldg_hint_u4(msg + (size_t)s0 * 128 + l16 * 8, pL);
        uint4 u1 = ldg_hint_u4(msg + (size_t)s1 * 128 + l16 * 8, pL);
        float2 f;
        f = __half22float2(*(__half2*)&u0.x); acc[0] += f.x; acc[1] += f.y;
        f = __half22float2(*(__half2*)&u0.y); acc[2] += f.x; acc[3] += f.y;
        f = __half22float2(*(__half2*)&u0.z); acc[4] += f.x; acc[5] += f.y;
        f = __half22float2(*(__half2*)&u0.w); acc[6] += f.x; acc[7] += f.y;
        f = __half22float2(*(__half2*)&u1.x); acc[0] += f.x; acc[1] += f.y;
        f = __half22float2(*(__half2*)&u1.y); acc[2] += f.x; acc[3] += f.y;
        f = __half22float2(*(__half2*)&u1.z); acc[4] += f.x; acc[5] += f.y;
        f = __half22float2(*(__half2*)&u1.w); acc[6] += f.x; acc[7] += f.y;
    }
    if (e < end) {
        int s0 = __ldg(&g_csr[e]);
        uint4 u0 = ldg_hint_u4(msg + (size_t)s0 * 128 + l16 * 8, pL);
        float2 f;
        f = __half22float2(*(__half2*)&u0.x); acc[0] += f.x; acc[1] += f.y;
        f = __half22float2(*(__half2*)&u0.y); acc[2] += f.x; acc[3] += f.y;
        f = __half22float2(*(__half2*)&u0.z); acc[4] += f.x; acc[5] += f.y;
        f = __half22float2(*(__half2*)&u0.w); acc[6] += f.x; acc[7] += f.y;
    }

    const float inv = 1.0f / fmaxf((float)(end - beg), 1.0f);
    const size_t base = (size_t)w * 128 + l16 * 8;
    float sf[8];
    if (selfh) {
        uint4 sh = ldg_hint_u4(selfh + base, pL);
        float2 f;
        f = __half22float2(*(__half2*)&sh.x); sf[0] = f.x; sf[1] = f.y;
        f = __half22float2(*(__half2*)&sh.y); sf[2] = f.x; sf[3] = f.y;
        f = __half22float2(*(__half2*)&sh.z); sf[4] = f.x; sf[5] = f.y;
        f = __half22float2(*(__half2*)&sh.w); sf[6] = f.x; sf[7] = f.y;
    } else {
        #pragma unroll
        for (int j = 0; j < 8; ++j) sf[j] = 0.f;
    }
    float o[8];
    #pragma unroll
    for (int j = 0; j < 8; ++j) o[j] = fmaf(acc[j], inv, sf[j]);
    if (relu) {
        #pragma unroll
        for (int j = 0; j < 8; ++j) o[j] = fmaxf(o[j], 0.f);
    }
    if (outf) {
        stg_hint_f4(outf + base,     make_float4(o[0], o[1], o[2], o[3]), pF);
        stg_hint_f4(outf + base + 4, make_float4(o[4], o[5], o[6], o[7]), pF);
    } else {
        uint4 p;
        __half2 t;
        t = __floats2half2_rn(o[0], o[1]); p.x = *(uint32_t*)&t;
        t = __floats2half2_rn(o[2], o[3]); p.y = *(uint32_t*)&t;
        t = __floats2half2_rn(o[4], o[5]); p.z = *(uint32_t*)&t;
        t = __floats2half2_rn(o[6], o[7]); p.w = *(uint32_t*)&t;
        *(uint4*)(outh + base) = p;
    }
}

// --------------------------------------------------------------------------------
extern "C" void kernel_launch(void* const* d_in, const int* in_sizes, int n_in,
                              void* d_out, int out_size)
{
    const float* x     = (const float*)d_in[0];
    const float* W_in  = (const float*)d_in[1];
    const float* W_out = (const float*)d_in[2];
    const int*   src   = (const int*)d_in[3];
    const int*   dst   = (const int*)d_in[4];
    float*       out   = (float*)d_out;

    const int N = in_sizes[0] / FEAT;
    const int E = in_sizes[3];

    __half *p_self, *p_msg, *p_msg2, *p_hh, *p_xh;
    int *p_deg;
    __half *p_B0, *p_B1;
    cudaGetSymbolAddress((void**)&p_self,  g_self);
    cudaGetSymbolAddress((void**)&p_msg,   g_msg);
    cudaGetSymbolAddress((void**)&p_msg2,  g_msg2);
    cudaGetSymbolAddress((void**)&p_hh,    g_hh);
    cudaGetSymbolAddress((void**)&p_xh,    g_xh);
    cudaGetSymbolAddress((void**)&p_deg,   g_deg);
    cudaGetSymbolAddress((void**)&p_B0,    g_B0);
    cudaGetSymbolAddress((void**)&p_B1,    g_B1);

    static bool s_init = false;
    static cudaStream_t s2 = 0;
    static cudaEvent_t evF = 0, evJ = 0, evM = 0, evS2 = 0;
    static cudaEvent_t evA[NCH], evB[NCH];
    static int n_sm = 148;
    if (!s_init) {
        cudaFuncSetAttribute(mma_gemm_kernel,
                             cudaFuncAttributeMaxDynamicSharedMemorySize,
                             SMEM_TOTAL_GEMM);
        cudaFuncSetAttribute(mma_gemm_n128_kernel,
                             cudaFuncAttributeMaxDynamicSharedMemorySize,
                             SMEM_TOTAL_N128);
        if (cudaStreamCreateWithFlags(&s2, cudaStreamNonBlocking) != cudaSuccess)
            s2 = 0;
        cudaEventCreateWithFlags(&evF,  cudaEventDisableTiming);
        cudaEventCreateWithFlags(&evJ,  cudaEventDisableTiming);
        cudaEventCreateWithFlags(&evM,  cudaEventDisableTiming);
        cudaEventCreateWithFlags(&evS2, cudaEventDisableTiming);
        for (int i = 0; i < NCH; ++i) {
            cudaEventCreateWithFlags(&evA[i], cudaEventDisableTiming);
            cudaEventCreateWithFlags(&evB[i], cudaEventDisableTiming);
        }
        cudaDeviceGetAttribute(&n_sm, cudaDevAttrMultiProcessorCount, 0);
        s_init = true;
    }

    const int egrid = (E + 255) / 256;
    const __half* B0L2 = p_B0 + 256 * 128;        // layer2, cols 0..255
    const __half* B1L2 = p_B1 + 256 * 128;
    const __half* B0L2msg = B0L2 + 128 * 128;     // layer2 msg cols (n 128..255)

    auto agg_grid = [](int nodes) { return (nodes + 7) / 8; };
    auto tiles = [](int rows) { return (rows + 127) / 128; };
    auto pgrid = [&](int nt) { return nt < n_sm ? nt : n_sm; };

    int b[NCH + 1];
    b[0] = 0;
    for (int i = 1; i < NCH; ++i) {
        long long r = (long long)N * i / NCH;
        b[i] = (int)((r + 127) / 128 * 128);
        if (b[i] > N) b[i] = N;
    }
    b[NCH] = N;

    // ---- fork: CSR build on s2; default: wprep -> xh -> gemm1 (launch #4) ----
    cudaEventRecord(evF, 0);
    cudaStreamWaitEvent(s2, evF, 0);
    zero_int_kernel<<<(N + 255) / 256, 256, 0, s2>>>(p_deg, N);          // #1
    wprep_kernel<<<(2 * 256 * 128 + 255) / 256, 256>>>(W_in, W_out);     // #2
    xh_kernel<<<(N * 32 + 255) / 256, 256>>>(x, N * 32);                 // #3
    {
        int nt = tiles(N);
        mma_gemm_kernel<<<pgrid(nt), GT, SMEM_TOTAL_GEMM>>>(             // #4
            p_xh, p_B0, p_B1, p_self, p_msg, 0, N, nt);
    }
    deg_kernel<<<egrid, 256, 0, s2>>>(dst, E);
    scan_kernel<<<1, 1024, 0, s2>>>(N);
    fill_kernel<<<egrid, 256, 0, s2>>>(src, dst, E);
    cudaEventRecord(evJ, s2);

    // ---- agg1 chunks (default): h = relu(self1 + mean(msg1)) -> fp16 hh ----
    cudaStreamWaitEvent(0, evJ, 0);
    for (int i = 0; i < NCH; ++i) {
        int nb = b[i], ne = b[i + 1];
        if (ne > nb)
            agg_csr_kernel<<<agg_grid(ne - nb), 128>>>(
                p_msg, p_self, nullptr, p_hh, nb, ne, 1);
        cudaEventRecord(evA[i], 0);
    }

    // ---- gemm2-msg chunks (s2): msg2 = hh @ W_out[1], fp16, 1 chain ----
    for (int i = 0; i < NCH; ++i) {
        int nb = b[i], ne = b[i + 1];
        if (ne <= nb) continue;
        cudaStreamWaitEvent(s2, evA[i], 0);
        int nt = tiles(ne - nb);
        mma_gemm_n128_kernel<<<pgrid(nt), GT, SMEM_TOTAL_N128, s2>>>(
            p_hh, B0L2msg, nullptr, nullptr, p_msg2, nb, N, nt);
    }
    cudaEventRecord(evM, s2);

    // ---- agg2-mean chunks (default): out = mean(msg2) (fp32) ----
    cudaStreamWaitEvent(0, evM, 0);
    for (int i = 0; i < NCH; ++i) {
        int nb = b[i], ne = b[i + 1];
        if (ne > nb)
            agg_csr_kernel<<<agg_grid(ne - nb), 128>>>(
                p_msg2, nullptr, out, nullptr, nb, ne, 0);
        cudaEventRecord(evB[i], 0);
    }

    // ---- gemm2-self chunks: out += hh @ W_out[0] (2 chains, fp32 RMW) ----
    // chunks 0..NCH-2 on s2 (overlap with agg2-mean), last chunk on default.
    for (int i = 0; i < NCH - 1; ++i) {
        int nb = b[i], ne = b[i + 1];
        if (ne <= nb) continue;
        cudaStreamWaitEvent(s2, evB[i], 0);
        int nt = tiles(ne - nb);
        mma_gemm_n128_kernel<<<pgrid(nt), GT, SMEM_TOTAL_N128, s2>>>(
            p_hh, B0L2, B1L2, out, nullptr, nb, N, nt);
    }
    cudaEventRecord(evS2, s2);
    cudaStreamWaitEvent(0, evS2, 0);              // join s2 back to default
    {
        int nb = b[NCH - 1], ne = b[NCH];
        if (ne > nb) {
            int nt = tiles(ne - nb);
            mma_gemm_n128_kernel<<<pgrid(nt), GT, SMEM_TOTAL_N128>>>(
                p_hh, B0L2, B1L2, out, nullptr, nb, N, nt);
        }
    }
}

// round 15
// speedup vs baseline: 1.0540x; 1.0540x over previous
#include <cuda_runtime.h>
#include <cuda_bf16.h>
#include <cuda_fp16.h>
#include <cstdint>

#define NNODES 100000
#define NEDGES 1600000
#define FEAT   128

// -------- scratch (static device globals; allocation-free per harness rules) ----
__device__ __align__(16) __half g_self  [NNODES * FEAT];  // layer1 self (fp16)
__device__ __align__(16) __half g_msg   [NNODES * FEAT];  // layer1 msg  (fp16)
__device__ __align__(16) __half g_self2h[NNODES * FEAT];  // layer2 self (fp16)
__device__ __align__(16) __half g_msg2  [NNODES * FEAT];  // layer2 msg  (fp16)
__device__ __align__(16) __half g_xh    [NNODES * FEAT];  // x rounded to fp16
__device__ int g_deg[NNODES];
__device__ int g_row_start[NNODES + 1];
__device__ int g_csr[NEDGES];
// fp16 split weights, pre-transposed to [layer][n(0..255)][k(0..127)]
__device__ __align__(16) __half g_B0[2 * 256 * 128];   // hi
__device__ __align__(16) __half g_B1[2 * 256 * 128];   // lo (residual)

// ================================ helpers =======================================
__device__ __forceinline__ uint32_t sm_u32(const void* p) {
    uint32_t a;
    asm("{ .reg .u64 t; cvta.to.shared.u64 t, %1; cvt.u32.u64 %0, t; }"
        : "=r"(a) : "l"(p));
    return a;
}
__device__ __forceinline__ void ldsm_x4(uint32_t* r, uint32_t addr) {
    asm volatile("ldmatrix.sync.aligned.m8n8.x4.shared.b16 {%0,%1,%2,%3}, [%4];"
                 : "=r"(r[0]), "=r"(r[1]), "=r"(r[2]), "=r"(r[3]) : "r"(addr));
}
__device__ __forceinline__ void mma16816(float* c, const uint32_t* a,
                                         uint32_t b0, uint32_t b1) {
    asm volatile("mma.sync.aligned.m16n8k16.row.col.f32.f16.f16.f32 "
                 "{%0,%1,%2,%3}, {%4,%5,%6,%7}, {%8,%9}, {%0,%1,%2,%3};"
                 : "+f"(c[0]), "+f"(c[1]), "+f"(c[2]), "+f"(c[3])
                 : "r"(a[0]), "r"(a[1]), "r"(a[2]), "r"(a[3]), "r"(b0), "r"(b1));
}
__device__ __forceinline__ void cp16(uint32_t saddr, const void* g, int src_sz) {
    asm volatile("cp.async.cg.shared.global [%0], [%1], 16, %2;"
                 :: "r"(saddr), "l"(g), "r"(src_sz) : "memory");
}
__device__ __forceinline__ void cp_commit() {
    asm volatile("cp.async.commit_group;" ::: "memory");
}
// ---- L2 eviction-priority via createpolicy + cache_hint ----
__device__ __forceinline__ uint64_t pol_evict_last() {
    uint64_t p;
    asm("createpolicy.fractional.L2::evict_last.b64 %0, 1.0;" : "=l"(p));
    return p;
}
__device__ __forceinline__ uint64_t pol_evict_first() {
    uint64_t p;
    asm("createpolicy.fractional.L2::evict_first.b64 %0, 1.0;" : "=l"(p));
    return p;
}
__device__ __forceinline__ uint4 ldg_hint_u4(const void* p, uint64_t pol) {
    uint4 v;
    asm volatile("ld.global.nc.L2::cache_hint.v4.u32 {%0,%1,%2,%3}, [%4], %5;"
                 : "=r"(v.x), "=r"(v.y), "=r"(v.z), "=r"(v.w) : "l"(p), "l"(pol));
    return v;
}
__device__ __forceinline__ void stg_hint_f4(void* p, float4 v, uint64_t pol) {
    asm volatile("st.global.L2::cache_hint.v4.f32 [%0], {%1,%2,%3,%4}, %5;"
                 :: "l"(p), "f"(v.x), "f"(v.y), "f"(v.z), "f"(v.w), "l"(pol)
                 : "memory");
}
__device__ __forceinline__ void stg_hint_u32(void* p, uint32_t v, uint64_t pol) {
    asm volatile("st.global.L2::cache_hint.u32 [%0], %1, %2;"
                 :: "l"(p), "r"(v), "l"(pol) : "memory");
}

// ============================= prep kernels (once) ==============================
__global__ void wprep_kernel(const float* __restrict__ W_in,
                             const float* __restrict__ W_out) {
    int idx = blockIdx.x * blockDim.x + threadIdx.x;
    if (idx >= 2 * 256 * 128) return;
    int layer = idx >> 15;
    int n = (idx >> 7) & 255;
    int k = idx & 127;
    const float* W = (layer ? W_out : W_in) + ((n >= 128) ? 128 * 128 : 0);
    float w = W[k * 128 + (n & 127)];
    __half w0 = __float2half_rn(w);
    __half w1 = __float2half_rn(w - __half2float(w0));
    g_B0[idx] = w0;
    g_B1[idx] = w1;
}
__global__ void xh_kernel(const float* __restrict__ x, int n4) {
    int i = blockIdx.x * blockDim.x + threadIdx.x;
    if (i >= n4) return;
    float4 v = ((const float4*)x)[i];
    __half2 t0 = __floats2half2_rn(v.x, v.y);
    __half2 t1 = __floats2half2_rn(v.z, v.w);
    uint2 p = make_uint2(*(uint32_t*)&t0, *(uint32_t*)&t1);
    ((uint2*)g_xh)[i] = p;
}

// =============================== CSR build ======================================
__global__ void zero_int_kernel(int* __restrict__ a, int n) {
    int i = blockIdx.x * blockDim.x + threadIdx.x;
    if (i < n) a[i] = 0;
}
__global__ void deg_kernel(const int* __restrict__ dst, int E) {
    int e = blockIdx.x * blockDim.x + threadIdx.x;
    if (e < E) atomicAdd(&g_deg[dst[e]], 1);
}
__global__ void scan_kernel(int n) {
    __shared__ int part[1024];
    const int T = 1024;
    int tid = threadIdx.x;
    int chunk = (n + T - 1) / T;
    int b = tid * chunk, e = min(b + chunk, n);
    int s = 0;
    for (int i = b; i < e; ++i) s += g_deg[i];
    part[tid] = s;
    __syncthreads();
    if (tid == 0) {
        int run = 0;
        for (int i = 0; i < T; ++i) { int t = part[i]; part[i] = run; run += t; }
    }
    __syncthreads();
    int run = part[tid];
    for (int i = b; i < e; ++i) { g_row_start[i] = run; run += g_deg[i]; }
    if (e == n) g_row_start[n] = run;
}
__global__ void fill_kernel(const int* __restrict__ src,
                            const int* __restrict__ dst, int E) {
    int e = blockIdx.x * blockDim.x + threadIdx.x;
    if (e < E) {
        int d = dst[e];
        int slot = g_row_start[d] + atomicSub(&g_deg[d], 1) - 1;
        g_csr[slot] = src[e];
    }
}

// ====== layer-1 persistent mma.sync dual GEMM, cp.async double-buffered A =======
#define GT 512
#define SM_A0  0                 // 32 KB
#define SM_A1  32768             // 32 KB
#define SM_BHI 65536             // 64 KB (256 rows)
#define SM_BLO 131072            // 32 KB (self half only)
#define SMEM_TOTAL_GEMM 163840

__device__ __forceinline__ void prefetch_A(uint32_t sb, int buf,
                                           const __half* __restrict__ feath,
                                           int row0, int nrows) {
    const uint32_t base = sb + (buf ? SM_A1 : SM_A0);
    int idx = threadIdx.x;
    #pragma unroll
    for (int j = 0; j < 4; ++j, idx += GT) {
        int r = idx >> 4, ch = idx & 15;
        int row = row0 + r;
        uint32_t off = r * 256 + ((ch ^ (r & 7)) << 4);
        cp16(base + off, feath + (size_t)row * 128 + ch * 8,
             (row < nrows) ? 16 : 0);
    }
}

__global__ __launch_bounds__(GT, 1)
void mma_gemm_kernel(const __half* __restrict__ feath,
                     const __half* __restrict__ Bg0,
                     const __half* __restrict__ Bg1,
                     __half* __restrict__ out_selfh,
                     __half* __restrict__ out_msg,
                     int nrows, int ntiles)
{
    extern __shared__ char smc[];
    const int tid = threadIdx.x;
    const uint32_t sb = sm_u32(smc);

    {
        int idx = tid;
        #pragma unroll
        for (int j = 0; j < 8; ++j, idx += GT) {
            int n = idx >> 4, ch = idx & 15;
            uint32_t off = n * 256 + ((ch ^ (n & 7)) << 4);
            cp16(sb + SM_BHI + off, Bg0 + n * 128 + ch * 8, 16);
        }
        idx = tid;
        #pragma unroll
        for (int j = 0; j < 4; ++j, idx += GT) {
            int n = idx >> 4, ch = idx & 15;
            uint32_t off = n * 256 + ((ch ^ (n & 7)) << 4);
            cp16(sb + SM_BLO + off, Bg1 + n * 128 + ch * 8, 16);
        }
    }
    int t = blockIdx.x;
    const int stride = gridDim.x;
    if (t < ntiles) prefetch_A(sb, 0, feath, t * 128, nrows);
    cp_commit();

    const int wid = tid >> 5, lane = tid & 31;
    const int mw = wid & 3;
    const int nw = wid >> 2;
    const bool self_half = (nw < 2);
    const int s3 = lane & 7, sel = lane >> 3;
    const int g = lane >> 2, tq = lane & 3;
    const int colhalf = (nw & 1) * 64;
    const uint64_t pL = pol_evict_last();

    int cur = 0;
    for (; t < ntiles; t += stride, cur ^= 1) {
        const int row0 = t * 128;
        const int nt_tile = t + stride;
        const bool has_next = (nt_tile < ntiles);

        if (has_next) {
            prefetch_A(sb, cur ^ 1, feath, nt_tile * 128, nrows);
            cp_commit();
            asm volatile("cp.async.wait_group 1;" ::: "memory");
        } else {
            asm volatile("cp.async.wait_group 0;" ::: "memory");
        }
        __syncthreads();

        const uint32_t abase = sb + (cur ? SM_A1 : SM_A0);

        float acc[2][8][4];
        #pragma unroll
        for (int a = 0; a < 2; ++a)
            #pragma unroll
            for (int b = 0; b < 8; ++b)
                #pragma unroll
                for (int c = 0; c < 4; ++c) acc[a][b][c] = 0.f;

        #pragma unroll
        for (int ks = 0; ks < 8; ++ks) {
            uint32_t ahi[2][4];
            #pragma unroll
            for (int mt = 0; mt < 2; ++mt) {
                int r = mw * 32 + mt * 16 + s3 + ((sel & 1) << 3);
                int ch = 2 * ks + (sel >> 1);
                uint32_t off = r * 256 + ((ch ^ (r & 7)) << 4);
                ldsm_x4(ahi[mt], abase + off);
            }
            #pragma unroll
            for (int jp = 0; jp < 4; ++jp) {
                int r = nw * 64 + jp * 16 + s3 + ((sel >> 1) << 3);
                int ch = 2 * ks + (sel & 1);
                uint32_t off = r * 256 + ((ch ^ (r & 7)) << 4);
                uint32_t bhi[4], blo[4];
                ldsm_x4(bhi, sb + SM_BHI + off);
                if (self_half) ldsm_x4(blo, sb + SM_BLO + off);
                #pragma unroll
                for (int tt = 0; tt < 2; ++tt) {
                    int nt = jp * 2 + tt;
                    #pragma unroll
                    for (int mt = 0; mt < 2; ++mt) {
                        mma16816(acc[mt][nt], ahi[mt], bhi[2*tt], bhi[2*tt+1]);
                        if (self_half)
                            mma16816(acc[mt][nt], ahi[mt], blo[2*tt], blo[2*tt+1]);
                    }
                }
            }
        }

        __half* dst = self_half ? out_selfh : out_msg;
        #pragma unroll
        for (int mt = 0; mt < 2; ++mt) {
            int rr = row0 + mw * 32 + mt * 16 + g;
            #pragma unroll
            for (int nt = 0; nt < 8; ++nt) {
                int col = colhalf + nt * 8 + 2 * tq;
                if (rr < nrows) {
                    __half2 h = __floats2half2_rn(acc[mt][nt][0], acc[mt][nt][1]);
                    stg_hint_u32(dst + (size_t)rr * 128 + col, *(uint32_t*)&h, pL);
                }
                if (rr + 8 < nrows) {
                    __half2 h = __floats2half2_rn(acc[mt][nt][2], acc[mt][nt][3]);
                    stg_hint_u32(dst + (size_t)(rr + 8) * 128 + col, *(uint32_t*)&h, pL);
                }
            }
        }
        __syncthreads();
    }
}

// ====== FUSED layer boundary: agg1 (gather-mean+self+relu) -> dual GEMM =========
// Per 128-node tile: phase 1 builds the h tile directly in the smem A buffer
// (fp16, swizzled — identical rounding to the old global h); phase 2 is the
// layer-2 dual GEMM. h never touches global memory. B tiles loaded once (persistent).
#define FSM_A   0                // 32 KB
#define FSM_BHI 32768            // 64 KB
#define FSM_BLO 98304            // 32 KB
#define FSMEM_TOTAL 131072

__global__ __launch_bounds__(GT, 1)
void fused_agg_gemm_kernel(const __half* __restrict__ msg1,
                           const __half* __restrict__ self1,
                           const __half* __restrict__ Bg0,
                           const __half* __restrict__ Bg1,
                           __half* __restrict__ out_self2,
                           __half* __restrict__ out_msg2,
                           int nrows, int ntiles)
{
    extern __shared__ char smc[];
    const int tid = threadIdx.x;
    const uint32_t sb = sm_u32(smc);
    const uint64_t pL = pol_evict_last();

    // ---- B tiles once per CTA (async; waited before first GEMM)
    {
        int idx = tid;
        #pragma unroll
        for (int j = 0; j < 8; ++j, idx += GT) {
            int n = idx >> 4, ch = idx & 15;
            uint32_t off = n * 256 + ((ch ^ (n & 7)) << 4);
            cp16(sb + FSM_BHI + off, Bg0 + n * 128 + ch * 8, 16);
        }
        idx = tid;
        #pragma unroll
        for (int j = 0; j < 4; ++j, idx += GT) {
            int n = idx >> 4, ch = idx & 15;
            uint32_t off = n * 256 + ((ch ^ (n & 7)) << 4);
            cp16(sb + FSM_BLO + off, Bg1 + n * 128 + ch * 8, 16);
        }
    }
    cp_commit();

    const int wid = tid >> 5, lane = tid & 31;
    const int hw = lane >> 4, l16 = lane & 15;
    const int mw = wid & 3;
    const int nw = wid >> 2;
    const bool self_half = (nw < 2);
    const int s3 = lane & 7, sel = lane >> 3;
    const int g = lane >> 2, tq = lane & 3;
    const int colhalf = (nw & 1) * 64;

    for (int t = blockIdx.x; t < ntiles; t += gridDim.x) {
        const int row0 = t * 128;

        // ================= phase 1: aggregate 128 nodes into smem A ============
        // warp handles 8 rows; pair (2 nodes x 16 lanes x LDG.128) per step.
        #pragma unroll 1
        for (int p = 0; p < 4; ++p) {
            const int r = wid * 8 + p * 2 + hw;
            const int node = row0 + r;
            float o[8];
            #pragma unroll
            for (int j = 0; j < 8; ++j) o[j] = 0.f;

            if (node < nrows) {
                const int beg = __ldg(&g_row_start[node]);
                const int end = __ldg(&g_row_start[node + 1]);
                float acc[8];
                #pragma unroll
                for (int j = 0; j < 8; ++j) acc[j] = 0.f;

                int e = beg;
                for (; e + 8 <= end; e += 8) {
                    int s[8];
                    #pragma unroll
                    for (int j = 0; j < 8; ++j) s[j] = __ldg(&g_csr[e + j]);
                    uint4 u[8];
                    #pragma unroll
                    for (int j = 0; j < 8; ++j)
                        u[j] = ldg_hint_u4(msg1 + (size_t)s[j] * 128 + l16 * 8, pL);
                    #pragma unroll
                    for (int j = 0; j < 8; ++j) {
                        float2 f;
                        f = __half22float2(*(__half2*)&u[j].x); acc[0] += f.x; acc[1] += f.y;
                        f = __half22float2(*(__half2*)&u[j].y); acc[2] += f.x; acc[3] += f.y;
                        f = __half22float2(*(__half2*)&u[j].z); acc[4] += f.x; acc[5] += f.y;
                        f = __half22float2(*(__half2*)&u[j].w); acc[6] += f.x; acc[7] += f.y;
                    }
                }
                for (; e < end; ++e) {
                    int s0 = __ldg(&g_csr[e]);
                    uint4 u0 = ldg_hint_u4(msg1 + (size_t)s0 * 128 + l16 * 8, pL);
                    float2 f;
                    f = __half22float2(*(__half2*)&u0.x); acc[0] += f.x; acc[1] += f.y;
                    f = __half22float2(*(__half2*)&u0.y); acc[2] += f.x; acc[3] += f.y;
                    f = __half22float2(*(__half2*)&u0.z); acc[4] += f.x; acc[5] += f.y;
                    f = __half22float2(*(__half2*)&u0.w); acc[6] += f.x; acc[7] += f.y;
                }

                const float inv = 1.0f / fmaxf((float)(end - beg), 1.0f);
                uint4 sh = ldg_hint_u4(self1 + (size_t)node * 128 + l16 * 8, pL);
                float2 f;
                f = __half22float2(*(__half2*)&sh.x);
                o[0] = fmaxf(fmaf(acc[0], inv, f.x), 0.f);
                o[1] = fmaxf(fmaf(acc[1], inv, f.y), 0.f);
                f = __half22float2(*(__half2*)&sh.y);
                o[2] = fmaxf(fmaf(acc[2], inv, f.x), 0.f);
                o[3] = fmaxf(fmaf(acc[3], inv, f.y), 0.f);
                f = __half22float2(*(__half2*)&sh.z);
                o[4] = fmaxf(fmaf(acc[4], inv, f.x), 0.f);
                o[5] = fmaxf(fmaf(acc[5], inv, f.y), 0.f);
                f = __half22float2(*(__half2*)&sh.w);
                o[6] = fmaxf(fmaf(acc[6], inv, f.x), 0.f);
                o[7] = fmaxf(fmaf(acc[7], inv, f.y), 0.f);
            }

            uint4 hp;
            __half2 ht;
            ht = __floats2half2_rn(o[0], o[1]); hp.x = *(uint32_t*)&ht;
            ht = __floats2half2_rn(o[2], o[3]); hp.y = *(uint32_t*)&ht;
            ht = __floats2half2_rn(o[4], o[5]); hp.z = *(uint32_t*)&ht;
            ht = __floats2half2_rn(o[6], o[7]); hp.w = *(uint32_t*)&ht;
            uint32_t off = r * 256 + ((l16 ^ (r & 7)) << 4);
            *(uint4*)(smc + FSM_A + off) = hp;
        }

        asm volatile("cp.async.wait_group 0;" ::: "memory");
        __syncthreads();

        // ================= phase 2: dual GEMM on the smem h tile ===============
        float acc[2][8][4];
        #pragma unroll
        for (int a = 0; a < 2; ++a)
            #pragma unroll
            for (int b = 0; b < 8; ++b)
                #pragma unroll
                for (int c = 0; c < 4; ++c) acc[a][b][c] = 0.f;

        #pragma unroll
        for (int ks = 0; ks < 8; ++ks) {
            uint32_t ahi[2][4];
            #pragma unroll
            for (int mt = 0; mt < 2; ++mt) {
                int r = mw * 32 + mt * 16 + s3 + ((sel & 1) << 3);
                int ch = 2 * ks + (sel >> 1);
                uint32_t off = r * 256 + ((ch ^ (r & 7)) << 4);
                ldsm_x4(ahi[mt], sb + FSM_A + off);
            }
            #pragma unroll
            for (int jp = 0; jp < 4; ++jp) {
                int r = nw * 64 + jp * 16 + s3 + ((sel >> 1) << 3);
                int ch = 2 * ks + (sel & 1);
                uint32_t off = r * 256 + ((ch ^ (r & 7)) << 4);
                uint32_t bhi[4], blo[4];
                ldsm_x4(bhi, sb + FSM_BHI + off);
                if (self_half) ldsm_x4(blo, sb + FSM_BLO + off);
                #pragma unroll
                for (int tt = 0; tt < 2; ++tt) {
                    int nt = jp * 2 + tt;
                    #pragma unroll
                    for (int mt = 0; mt < 2; ++mt) {
                        mma16816(acc[mt][nt], ahi[mt], bhi[2*tt], bhi[2*tt+1]);
                        if (self_half)
                            mma16816(acc[mt][nt], ahi[mt], blo[2*tt], blo[2*tt+1]);
                    }
                }
            }
        }

        __half* dst = self_half ? out_self2 : out_msg2;
        #pragma unroll
        for (int mt = 0; mt < 2; ++mt) {
            int rr = row0 + mw * 32 + mt * 16 + g;
            #pragma unroll
            for (int nt = 0; nt < 8; ++nt) {
                int col = colhalf + nt * 8 + 2 * tq;
                if (rr < nrows) {
                    __half2 h = __floats2half2_rn(acc[mt][nt][0], acc[mt][nt][1]);
                    stg_hint_u32(dst + (size_t)rr * 128 + col, *(uint32_t*)&h, pL);
                }
                if (rr + 8 < nrows) {
                    __half2 h = __floats2half2_rn(acc[mt][nt][2], acc[mt][nt][3]);
                    stg_hint_u32(dst + (size_t)(rr + 8) * 128 + col, *(uint32_t*)&h, pL);
                }
            }
        }
        __syncthreads();
    }
}

// -------- final agg: out = self2(fp16) + mean(gather msg2), fp32 out ------------
__global__ void agg_out_kernel(const __half* __restrict__ msg,
                               const __half* __restrict__ selfh,
                               float* __restrict__ outf,
                               int N)
{
    const int gwarp = (blockIdx.x * blockDim.x + threadIdx.x) >> 5;
    const int lane = threadIdx.x & 31;
    const int hw = lane >> 4;
    const int l16 = lane & 15;
    const int w = gwarp * 2 + hw;
    if (w >= N) return;

    const uint64_t pL = pol_evict_last();
    const uint64_t pF = pol_evict_first();

    const int beg = __ldg(&g_row_start[w]);
    const int end = __ldg(&g_row_start[w + 1]);

    float acc[8];
    #pragma unroll
    for (int j = 0; j < 8; ++j) acc[j] = 0.f;

    int e = beg;
    for (; e + 8 <= end; e += 8) {
        int s[8];
        #pragma unroll
        for (int j = 0; j < 8; ++j) s[j] = __ldg(&g_csr[e + j]);
        uint4 u[8];
        #pragma unroll
        for (int j = 0; j < 8; ++j)
            u[j] = ldg_hint_u4(msg + (size_t)s[j] * 128 + l16 * 8, pL);
        #pragma unroll
        for (int j = 0; j < 8; ++j) {
            float2 f;
            f = __half22float2(*(__half2*)&u[j].x); acc[0] += f.x; acc[1] += f.y;
            f = __half22float2(*(__half2*)&u[j].y); acc[2] += f.x; acc[3] += f.y;
            f = __half22float2(*(__half2*)&u[j].z); acc[4] += f.x; acc[5] += f.y;
            f = __half22float2(*(__half2*)&u[j].w); acc[6] += f.x; acc[7] += f.y;
        }
    }
    for (; e < end; ++e) {
        int s0 = __ldg(&g_csr[e]);
        uint4 u0 = ldg_hint_u4(msg + (size_t)s0 * 128 + l16 * 8, pL);
        float2 f;
        f = __half22float2(*(__half2*)&u0.x); acc[0] += f.x; acc[1] += f.y;
        f = __half22float2(*(__half2*)&u0.y); acc[2] += f.x; acc[3] += f.y;
        f = __half22float2(*(__half2*)&u0.z); acc[4] += f.x; acc[5] += f.y;
        f = __half22float2(*(__half2*)&u0.w); acc[6] += f.x; acc[7] += f.y;
    }

    const float inv = 1.0f / fmaxf((float)(end - beg), 1.0f);
    const size_t base = (size_t)w * 128 + l16 * 8;
    uint4 sh = ldg_hint_u4(selfh + base, pL);
    float sf[8];
    float2 f;
    f = __half22float2(*(__half2*)&sh.x); sf[0] = f.x; sf[1] = f.y;
    f = __half22float2(*(__half2*)&sh.y); sf[2] = f.x; sf[3] = f.y;
    f = __half22float2(*(__half2*)&sh.z); sf[4] = f.x; sf[5] = f.y;
    f = __half22float2(*(__half2*)&sh.w); sf[6] = f.x; sf[7] = f.y;

    float o[8];
    #pragma unroll
    for (int j = 0; j < 8; ++j) o[j] = fmaf(acc[j], inv, sf[j]);
    stg_hint_f4(outf + base,     make_float4(o[0], o[1], o[2], o[3]), pF);
    stg_hint_f4(outf + base + 4, make_float4(o[4], o[5], o[6], o[7]), pF);
}

// --------------------------------------------------------------------------------
extern "C" void kernel_launch(void* const* d_in, const int* in_sizes, int n_in,
                              void* d_out, int out_size)
{
    const float* x     = (const float*)d_in[0];
    const float* W_in  = (const float*)d_in[1];
    const float* W_out = (const float*)d_in[2];
    const int*   src   = (const int*)d_in[3];
    const int*   dst   = (const int*)d_in[4];
    float*       out   = (float*)d_out;

    const int N = in_sizes[0] / FEAT;
    const int E = in_sizes[3];

    __half *p_self, *p_msg, *p_self2h, *p_msg2, *p_xh;
    int *p_deg;
    __half *p_B0, *p_B1;
    cudaGetSymbolAddress((void**)&p_self,   g_self);
    cudaGetSymbolAddress((void**)&p_msg,    g_msg);
    cudaGetSymbolAddress((void**)&p_self2h, g_self2h);
    cudaGetSymbolAddress((void**)&p_msg2,   g_msg2);
    cudaGetSymbolAddress((void**)&p_xh,     g_xh);
    cudaGetSymbolAddress((void**)&p_deg,    g_deg);
    cudaGetSymbolAddress((void**)&p_B0,     g_B0);
    cudaGetSymbolAddress((void**)&p_B1,     g_B1);

    static bool s_init = false;
    static cudaStream_t s2 = 0;
    static cudaEvent_t evF = 0, evJ = 0;
    static int n_sm = 148;
    if (!s_init) {
        cudaFuncSetAttribute(mma_gemm_kernel,
                             cudaFuncAttributeMaxDynamicSharedMemorySize,
                             SMEM_TOTAL_GEMM);
        cudaFuncSetAttribute(fused_agg_gemm_kernel,
                             cudaFuncAttributeMaxDynamicSharedMemorySize,
                             FSMEM_TOTAL);
        if (cudaStreamCreateWithFlags(&s2, cudaStreamNonBlocking) != cudaSuccess)
            s2 = 0;
        cudaEventCreateWithFlags(&evF, cudaEventDisableTiming);
        cudaEventCreateWithFlags(&evJ, cudaEventDisableTiming);
        cudaDeviceGetAttribute(&n_sm, cudaDevAttrMultiProcessorCount, 0);
        s_init = true;
    }

    const int egrid = (E + 255) / 256;
    const __half* B0L2 = p_B0 + 256 * 128;
    const __half* B1L2 = p_B1 + 256 * 128;

    const int ntiles = (N + 127) / 128;
    const int pg = (ntiles < n_sm) ? ntiles : n_sm;

    // ---- fork: CSR build on s2; default: wprep -> xh -> gemm1 (launch #4) ----
    cudaEventRecord(evF, 0);
    cudaStreamWaitEvent(s2, evF, 0);
    zero_int_kernel<<<(N + 255) / 256, 256, 0, s2>>>(p_deg, N);          // #1
    wprep_kernel<<<(2 * 256 * 128 + 255) / 256, 256>>>(W_in, W_out);     // #2
    xh_kernel<<<(N * 32 + 255) / 256, 256>>>(x, N * 32);                 // #3
    mma_gemm_kernel<<<pg, GT, SMEM_TOTAL_GEMM>>>(                        // #4
        p_xh, p_B0, p_B1, p_self, p_msg, N, ntiles);
    deg_kernel<<<egrid, 256, 0, s2>>>(dst, E);
    scan_kernel<<<1, 1024, 0, s2>>>(N);
    fill_kernel<<<egrid, 256, 0, s2>>>(src, dst, E);
    cudaEventRecord(evJ, s2);

    // ---- fused layer boundary: agg1 + gemm2 in one persistent kernel ----
    cudaStreamWaitEvent(0, evJ, 0);
    fused_agg_gemm_kernel<<<pg, GT, FSMEM_TOTAL>>>(
        p_msg, p_self, B0L2, B1L2, p_self2h, p_msg2, N, ntiles);

    // ---- final aggregation: out = self2 + mean(msg2) ----
    agg_out_kernel<<<(N + 7) / 8, 128>>>(p_msg2, p_self2h, out, N);
}

// round 16
// speedup vs baseline: 1.1345x; 1.0764x over previous
#include <cuda_runtime.h>
#include <cuda_bf16.h>
#include <cuda_fp16.h>
#include <cstdint>

#define NNODES 100000
#define NEDGES 1600000
#define FEAT   128

// -------- scratch (static device globals; allocation-free per harness rules) ----
__device__ __align__(16) __half g_self  [NNODES * FEAT];  // layer1 self (fp16)
__device__ __align__(16) __half g_msg   [NNODES * FEAT];  // layer1 msg  (fp16)
__device__ __align__(16) __half g_hh    [NNODES * FEAT];  // hidden h    (fp16)
__device__ __align__(16) __half g_self2h[NNODES * FEAT];  // layer2 self (fp16)
__device__ __align__(16) __half g_msg2  [NNODES * FEAT];  // layer2 msg  (fp16)
__device__ __align__(16) __half g_xh    [NNODES * FEAT];  // x rounded to fp16
__device__ int g_deg[NNODES];
__device__ int g_row_start[NNODES + 1];
__device__ int g_csr[NEDGES];
// fp16 split weights, pre-transposed to [layer][n(0..255)][k(0..127)]
__device__ __align__(16) __half g_B0[2 * 256 * 128];   // hi
__device__ __align__(16) __half g_B1[2 * 256 * 128];   // lo (residual)

// ================================ helpers =======================================
__device__ __forceinline__ uint32_t sm_u32(const void* p) {
    uint32_t a;
    asm("{ .reg .u64 t; cvta.to.shared.u64 t, %1; cvt.u32.u64 %0, t; }"
        : "=r"(a) : "l"(p));
    return a;
}
__device__ __forceinline__ void ldsm_x4(uint32_t* r, uint32_t addr) {
    asm volatile("ldmatrix.sync.aligned.m8n8.x4.shared.b16 {%0,%1,%2,%3}, [%4];"
                 : "=r"(r[0]), "=r"(r[1]), "=r"(r[2]), "=r"(r[3]) : "r"(addr));
}
__device__ __forceinline__ void mma16816(float* c, const uint32_t* a,
                                         uint32_t b0, uint32_t b1) {
    asm volatile("mma.sync.aligned.m16n8k16.row.col.f32.f16.f16.f32 "
                 "{%0,%1,%2,%3}, {%4,%5,%6,%7}, {%8,%9}, {%0,%1,%2,%3};"
                 : "+f"(c[0]), "+f"(c[1]), "+f"(c[2]), "+f"(c[3])
                 : "r"(a[0]), "r"(a[1]), "r"(a[2]), "r"(a[3]), "r"(b0), "r"(b1));
}
__device__ __forceinline__ void cp16(uint32_t saddr, const void* g, int src_sz) {
    asm volatile("cp.async.cg.shared.global [%0], [%1], 16, %2;"
                 :: "r"(saddr), "l"(g), "r"(src_sz) : "memory");
}
__device__ __forceinline__ void cp_commit() {
    asm volatile("cp.async.commit_group;" ::: "memory");
}
// gather load: L2-only (.cg — no L1 allocation; gathered rows have no L1 reuse)
__device__ __forceinline__ uint4 ldg_cg_u4(const void* p) {
    uint4 v;
    asm volatile("ld.global.cg.v4.u32 {%0,%1,%2,%3}, [%4];"
                 : "=r"(v.x), "=r"(v.y), "=r"(v.z), "=r"(v.w) : "l"(p));
    return v;
}

// ============================= prep kernels (once) ==============================
__global__ void wprep_kernel(const float* __restrict__ W_in,
                             const float* __restrict__ W_out) {
    int idx = blockIdx.x * blockDim.x + threadIdx.x;
    if (idx >= 2 * 256 * 128) return;
    int layer = idx >> 15;
    int n = (idx >> 7) & 255;
    int k = idx & 127;
    const float* W = (layer ? W_out : W_in) + ((n >= 128) ? 128 * 128 : 0);
    float w = W[k * 128 + (n & 127)];
    __half w0 = __float2half_rn(w);
    __half w1 = __float2half_rn(w - __half2float(w0));
    g_B0[idx] = w0;
    g_B1[idx] = w1;
}
__global__ void xh_kernel(const float* __restrict__ x, int n4) {
    int i = blockIdx.x * blockDim.x + threadIdx.x;
    if (i >= n4) return;
    float4 v = ((const float4*)x)[i];
    __half2 t0 = __floats2half2_rn(v.x, v.y);
    __half2 t1 = __floats2half2_rn(v.z, v.w);
    uint2 p = make_uint2(*(uint32_t*)&t0, *(uint32_t*)&t1);
    ((uint2*)g_xh)[i] = p;
}

// =============================== CSR build ======================================
__global__ void zero_int_kernel(int* __restrict__ a, int n) {
    int i = blockIdx.x * blockDim.x + threadIdx.x;
    if (i < n) a[i] = 0;
}
__global__ void deg_kernel(const int* __restrict__ dst, int E) {
    int e = blockIdx.x * blockDim.x + threadIdx.x;
    if (e < E) atomicAdd(&g_deg[dst[e]], 1);
}
__global__ void scan_kernel(int n) {
    __shared__ int part[1024];
    const int T = 1024;
    int tid = threadIdx.x;
    int chunk = (n + T - 1) / T;
    int b = tid * chunk, e = min(b + chunk, n);
    int s = 0;
    for (int i = b; i < e; ++i) s += g_deg[i];
    part[tid] = s;
    __syncthreads();
    if (tid == 0) {
        int run = 0;
        for (int i = 0; i < T; ++i) { int t = part[i]; part[i] = run; run += t; }
    }
    __syncthreads();
    int run = part[tid];
    for (int i = b; i < e; ++i) { g_row_start[i] = run; run += g_deg[i]; }
    if (e == n) g_row_start[n] = run;
}
__global__ void fill_kernel(const int* __restrict__ src,
                            const int* __restrict__ dst, int E) {
    int e = blockIdx.x * blockDim.x + threadIdx.x;
    if (e < E) {
        int d = dst[e];
        int slot = g_row_start[d] + atomicSub(&g_deg[d], 1) - 1;
        g_csr[slot] = src[e];
    }
}

// ====== layer-1 persistent mma.sync dual GEMM (N=256), cp.async pipelined =======
#define GT 512
#define SM_A0  0                 // 32 KB
#define SM_A1  32768             // 32 KB
#define SM_BHI 65536             // 64 KB (256 rows)
#define SM_BLO 131072            // 32 KB (self half only)
#define SMEM_TOTAL_GEMM 163840

__device__ __forceinline__ void prefetch_A(uint32_t sb, int buf,
                                           const __half* __restrict__ feath,
                                           int row0, int nrows) {
    const uint32_t base = sb + (buf ? SM_A1 : SM_A0);
    int idx = threadIdx.x;
    #pragma unroll
    for (int j = 0; j < 4; ++j, idx += GT) {
        int r = idx >> 4, ch = idx & 15;
        int row = row0 + r;
        uint32_t off = r * 256 + ((ch ^ (r & 7)) << 4);
        cp16(base + off, feath + (size_t)row * 128 + ch * 8,
             (row < nrows) ? 16 : 0);
    }
}

__global__ __launch_bounds__(GT, 1)
void mma_gemm_kernel(const __half* __restrict__ feath,
                     const __half* __restrict__ Bg0,
                     const __half* __restrict__ Bg1,
                     __half* __restrict__ out_selfh,
                     __half* __restrict__ out_msg,
                     int nrows, int ntiles)
{
    extern __shared__ char smc[];
    const int tid = threadIdx.x;
    const uint32_t sb = sm_u32(smc);

    {
        int idx = tid;
        #pragma unroll
        for (int j = 0; j < 8; ++j, idx += GT) {
            int n = idx >> 4, ch = idx & 15;
            uint32_t off = n * 256 + ((ch ^ (n & 7)) << 4);
            cp16(sb + SM_BHI + off, Bg0 + n * 128 + ch * 8, 16);
        }
        idx = tid;
        #pragma unroll
        for (int j = 0; j < 4; ++j, idx += GT) {
            int n = idx >> 4, ch = idx & 15;
            uint32_t off = n * 256 + ((ch ^ (n & 7)) << 4);
            cp16(sb + SM_BLO + off, Bg1 + n * 128 + ch * 8, 16);
        }
    }
    int t = blockIdx.x;
    const int stride = gridDim.x;
    if (t < ntiles) prefetch_A(sb, 0, feath, t * 128, nrows);
    cp_commit();

    const int wid = tid >> 5, lane = tid & 31;
    const int mw = wid & 3;
    const int nw = wid >> 2;
    const bool self_half = (nw < 2);
    const int s3 = lane & 7, sel = lane >> 3;
    const int g = lane >> 2, tq = lane & 3;
    const int colhalf = (nw & 1) * 64;

    int cur = 0;
    for (; t < ntiles; t += stride, cur ^= 1) {
        const int row0 = t * 128;
        const int nt_tile = t + stride;
        const bool has_next = (nt_tile < ntiles);

        if (has_next) {
            prefetch_A(sb, cur ^ 1, feath, nt_tile * 128, nrows);
            cp_commit();
            asm volatile("cp.async.wait_group 1;" ::: "memory");
        } else {
            asm volatile("cp.async.wait_group 0;" ::: "memory");
        }
        __syncthreads();

        const uint32_t abase = sb + (cur ? SM_A1 : SM_A0);

        float acc[2][8][4];
        #pragma unroll
        for (int a = 0; a < 2; ++a)
            #pragma unroll
            for (int b = 0; b < 8; ++b)
                #pragma unroll
                for (int c = 0; c < 4; ++c) acc[a][b][c] = 0.f;

        #pragma unroll
        for (int ks = 0; ks < 8; ++ks) {
            uint32_t ahi[2][4];
            #pragma unroll
            for (int mt = 0; mt < 2; ++mt) {
                int r = mw * 32 + mt * 16 + s3 + ((sel & 1) << 3);
                int ch = 2 * ks + (sel >> 1);
                uint32_t off = r * 256 + ((ch ^ (r & 7)) << 4);
                ldsm_x4(ahi[mt], abase + off);
            }
            #pragma unroll
            for (int jp = 0; jp < 4; ++jp) {
                int r = nw * 64 + jp * 16 + s3 + ((sel >> 1) << 3);
                int ch = 2 * ks + (sel & 1);
                uint32_t off = r * 256 + ((ch ^ (r & 7)) << 4);
                uint32_t bhi[4], blo[4];
                ldsm_x4(bhi, sb + SM_BHI + off);
                if (self_half) ldsm_x4(blo, sb + SM_BLO + off);
                #pragma unroll
                for (int tt = 0; tt < 2; ++tt) {
                    int nt = jp * 2 + tt;
                    #pragma unroll
                    for (int mt = 0; mt < 2; ++mt) {
                        mma16816(acc[mt][nt], ahi[mt], bhi[2*tt], bhi[2*tt+1]);
                        if (self_half)
                            mma16816(acc[mt][nt], ahi[mt], blo[2*tt], blo[2*tt+1]);
                    }
                }
            }
        }

        __half* dst = self_half ? out_selfh : out_msg;
        #pragma unroll
        for (int mt = 0; mt < 2; ++mt) {
            int rr = row0 + mw * 32 + mt * 16 + g;
            #pragma unroll
            for (int nt = 0; nt < 8; ++nt) {
                int col = colhalf + nt * 8 + 2 * tq;
                if (rr < nrows)
                    *(__half2*)(dst + (size_t)rr * 128 + col) =
                        __floats2half2_rn(acc[mt][nt][0], acc[mt][nt][1]);
                if (rr + 8 < nrows)
                    *(__half2*)(dst + (size_t)(rr + 8) * 128 + col) =
                        __floats2half2_rn(acc[mt][nt][2], acc[mt][nt][3]);
            }
        }
        __syncthreads();
    }
}

// ====== persistent mma.sync GEMM, N=128 (layer-2 halves), fp16 out ==============
// Bg1 == null -> 1 chain (msg half). Bg1 != null -> 2 chains (self half).
#define SMN_BHI 65536            // 32 KB (128 rows)
#define SMN_BLO 98304            // 32 KB
#define SMEM_TOTAL_N128 131072

__global__ __launch_bounds__(GT, 1)
void mma_gemm_n128_kernel(const __half* __restrict__ feath,
                          const __half* __restrict__ Bg0,
                          const __half* __restrict__ Bg1,
                          __half* __restrict__ outh,
                          int row_base, int nrows, int ntiles)
{
    extern __shared__ char smc[];
    const int tid = threadIdx.x;
    const uint32_t sb = sm_u32(smc);
    const bool two_chain = (Bg1 != nullptr);

    {
        int idx = tid;
        #pragma unroll
        for (int j = 0; j < 4; ++j, idx += GT) {
            int n = idx >> 4, ch = idx & 15;
            uint32_t off = n * 256 + ((ch ^ (n & 7)) << 4);
            cp16(sb + SMN_BHI + off, Bg0 + n * 128 + ch * 8, 16);
        }
        if (two_chain) {
            idx = tid;
            #pragma unroll
            for (int j = 0; j < 4; ++j, idx += GT) {
                int n = idx >> 4, ch = idx & 15;
                uint32_t off = n * 256 + ((ch ^ (n & 7)) << 4);
                cp16(sb + SMN_BLO + off, Bg1 + n * 128 + ch * 8, 16);
            }
        }
    }
    int t = blockIdx.x;
    const int stride = gridDim.x;
    if (t < ntiles) prefetch_A(sb, 0, feath, row_base + t * 128, nrows);
    cp_commit();

    const int wid = tid >> 5, lane = tid & 31;
    const int mw = wid & 3;
    const int nw = wid >> 2;
    const int s3 = lane & 7, sel = lane >> 3;
    const int g = lane >> 2, tq = lane & 3;

    int cur = 0;
    for (; t < ntiles; t += stride, cur ^= 1) {
        const int row0 = row_base + t * 128;
        const int nt_tile = t + stride;
        const bool has_next = (nt_tile < ntiles);

        if (has_next) {
            prefetch_A(sb, cur ^ 1, feath, row_base + nt_tile * 128, nrows);
            cp_commit();
            asm volatile("cp.async.wait_group 1;" ::: "memory");
        } else {
            asm volatile("cp.async.wait_group 0;" ::: "memory");
        }
        __syncthreads();

        const uint32_t abase = sb + (cur ? SM_A1 : SM_A0);

        float acc[2][4][4];
        #pragma unroll
        for (int a = 0; a < 2; ++a)
            #pragma unroll
            for (int b = 0; b < 4; ++b)
                #pragma unroll
                for (int c = 0; c < 4; ++c) acc[a][b][c] = 0.f;

        #pragma unroll
        for (int ks = 0; ks < 8; ++ks) {
            uint32_t ahi[2][4];
            #pragma unroll
            for (int mt = 0; mt < 2; ++mt) {
                int r = mw * 32 + mt * 16 + s3 + ((sel & 1) << 3);
                int ch = 2 * ks + (sel >> 1);
                uint32_t off = r * 256 + ((ch ^ (r & 7)) << 4);
                ldsm_x4(ahi[mt], abase + off);
            }
            #pragma unroll
            for (int jp = 0; jp < 2; ++jp) {
                int r = nw * 32 + jp * 16 + s3 + ((sel >> 1) << 3);
                int ch = 2 * ks + (sel & 1);
                uint32_t off = r * 256 + ((ch ^ (r & 7)) << 4);
                uint32_t bhi[4], blo[4];
                ldsm_x4(bhi, sb + SMN_BHI + off);
                if (two_chain) ldsm_x4(blo, sb + SMN_BLO + off);
                #pragma unroll
                for (int tt = 0; tt < 2; ++tt) {
                    int nt = jp * 2 + tt;
                    #pragma unroll
                    for (int mt = 0; mt < 2; ++mt) {
                        mma16816(acc[mt][nt], ahi[mt], bhi[2*tt], bhi[2*tt+1]);
                        if (two_chain)
                            mma16816(acc[mt][nt], ahi[mt], blo[2*tt], blo[2*tt+1]);
                    }
                }
            }
        }

        #pragma unroll
        for (int mt = 0; mt < 2; ++mt) {
            int rr = row0 + mw * 32 + mt * 16 + g;
            #pragma unroll
            for (int nt = 0; nt < 4; ++nt) {
                int col = nw * 32 + nt * 8 + 2 * tq;
                if (rr < nrows)
                    *(__half2*)(outh + (size_t)rr * 128 + col) =
                        __floats2half2_rn(acc[mt][nt][0], acc[mt][nt][1]);
                if (rr + 8 < nrows)
                    *(__half2*)(outh + (size_t)(rr + 8) * 128 + col) =
                        __floats2half2_rn(acc[mt][nt][2], acc[mt][nt][3]);
            }
        }
        __syncthreads();
    }
}

// ------- CSR gather-mean: 2 dst-nodes per warp, 16 lanes x LDG.128 (.cg) --------
// out = relu?(selfh + mean(gather msg)); fp16 out via outh, fp32 via outf.
__global__ void agg_csr_kernel(const __half* __restrict__ msg,
                               const __half* __restrict__ selfh,
                               float* __restrict__ outf,
                               __half* __restrict__ outh,
                               int node_base, int node_end, int relu)
{
    const int gwarp = (blockIdx.x * blockDim.x + threadIdx.x) >> 5;
    const int lane = threadIdx.x & 31;
    const int hw = lane >> 4;
    const int l16 = lane & 15;
    const int w = node_base + gwarp * 2 + hw;
    if (w >= node_end) return;

    const int beg = __ldg(&g_row_start[w]);
    const int end = __ldg(&g_row_start[w + 1]);

    float acc[8];
    #pragma unroll
    for (int j = 0; j < 8; ++j) acc[j] = 0.f;

    int e = beg;
    for (; e + 8 <= end; e += 8) {
        int s[8];
        #pragma unroll
        for (int j = 0; j < 8; ++j) s[j] = __ldg(&g_csr[e + j]);
        uint4 u[8];
        #pragma unroll
        for (int j = 0; j < 8; ++j)
            u[j] = ldg_cg_u4(msg + (size_t)s[j] * 128 + l16 * 8);
        #pragma unroll
        for (int j = 0; j < 8; ++j) {
            float2 f;
            f = __half22float2(*(__half2*)&u[j].x); acc[0] += f.x; acc[1] += f.y;
            f = __half22float2(*(__half2*)&u[j].y); acc[2] += f.x; acc[3] += f.y;
            f = __half22float2(*(__half2*)&u[j].z); acc[4] += f.x; acc[5] += f.y;
            f = __half22float2(*(__half2*)&u[j].w); acc[6] += f.x; acc[7] += f.y;
        }
    }
    for (; e < end; ++e) {
        int s0 = __ldg(&g_csr[e]);
        uint4 u0 = ldg_cg_u4(msg + (size_t)s0 * 128 + l16 * 8);
        float2 f;
        f = __half22float2(*(__half2*)&u0.x); acc[0] += f.x; acc[1] += f.y;
        f = __half22float2(*(__half2*)&u0.y); acc[2] += f.x; acc[3] += f.y;
        f = __half22float2(*(__half2*)&u0.z); acc[4] += f.x; acc[5] += f.y;
        f = __half22float2(*(__half2*)&u0.w); acc[6] += f.x; acc[7] += f.y;
    }

    const float inv = 1.0f / fmaxf((float)(end - beg), 1.0f);
    const size_t base = (size_t)w * 128 + l16 * 8;
    uint4 sh = *(const uint4*)(selfh + base);
    float sf[8];
    float2 f;
    f = __half22float2(*(__half2*)&sh.x); sf[0] = f.x; sf[1] = f.y;
    f = __half22float2(*(__half2*)&sh.y); sf[2] = f.x; sf[3] = f.y;
    f = __half22float2(*(__half2*)&sh.z); sf[4] = f.x; sf[5] = f.y;
    f = __half22float2(*(__half2*)&sh.w); sf[6] = f.x; sf[7] = f.y;

    float o[8];
    #pragma unroll
    for (int j = 0; j < 8; ++j) o[j] = fmaf(acc[j], inv, sf[j]);
    if (relu) {
        #pragma unroll
        for (int j = 0; j < 8; ++j) o[j] = fmaxf(o[j], 0.f);
    }
    if (outf) {
        *(float4*)(outf + base)     = make_float4(o[0], o[1], o[2], o[3]);
        *(float4*)(outf + base + 4) = make_float4(o[4], o[5], o[6], o[7]);
    } else {
        uint4 p;
        __half2 t;
        t = __floats2half2_rn(o[0], o[1]); p.x = *(uint32_t*)&t;
        t = __floats2half2_rn(o[2], o[3]); p.y = *(uint32_t*)&t;
        t = __floats2half2_rn(o[4], o[5]); p.z = *(uint32_t*)&t;
        t = __floats2half2_rn(o[6], o[7]); p.w = *(uint32_t*)&t;
        *(uint4*)(outh + base) = p;
    }
}

// --------------------------------------------------------------------------------
extern "C" void kernel_launch(void* const* d_in, const int* in_sizes, int n_in,
                              void* d_out, int out_size)
{
    const float* x     = (const float*)d_in[0];
    const float* W_in  = (const float*)d_in[1];
    const float* W_out = (const float*)d_in[2];
    const int*   src   = (const int*)d_in[3];
    const int*   dst   = (const int*)d_in[4];
    float*       out   = (float*)d_out;

    const int N = in_sizes[0] / FEAT;
    const int E = in_sizes[3];
    const int Nh = ((N / 2 + 127) / 128) * 128;   // chunk boundary

    __half *p_self, *p_msg, *p_hh, *p_self2h, *p_msg2, *p_xh;
    int *p_deg;
    __half *p_B0, *p_B1;
    cudaGetSymbolAddress((void**)&p_self,   g_self);
    cudaGetSymbolAddress((void**)&p_msg,    g_msg);
    cudaGetSymbolAddress((void**)&p_hh,     g_hh);
    cudaGetSymbolAddress((void**)&p_self2h, g_self2h);
    cudaGetSymbolAddress((void**)&p_msg2,   g_msg2);
    cudaGetSymbolAddress((void**)&p_xh,     g_xh);
    cudaGetSymbolAddress((void**)&p_deg,    g_deg);
    cudaGetSymbolAddress((void**)&p_B0,     g_B0);
    cudaGetSymbolAddress((void**)&p_B1,     g_B1);

    static bool s_init = false;
    static cudaStream_t s2 = 0;
    static cudaEvent_t evF = 0, evJ = 0, evA0 = 0, evA1 = 0;
    static cudaEvent_t evM = 0, evS0 = 0, evS1 = 0;
    static int n_sm = 148;
    if (!s_init) {
        cudaFuncSetAttribute(mma_gemm_kernel,
                             cudaFuncAttributeMaxDynamicSharedMemorySize,
                             SMEM_TOTAL_GEMM);
        cudaFuncSetAttribute(mma_gemm_n128_kernel,
                             cudaFuncAttributeMaxDynamicSharedMemorySize,
                             SMEM_TOTAL_N128);
        if (cudaStreamCreateWithFlags(&s2, cudaStreamNonBlocking) != cudaSuccess)
            s2 = 0;
        cudaEventCreateWithFlags(&evF,  cudaEventDisableTiming);
        cudaEventCreateWithFlags(&evJ,  cudaEventDisableTiming);
        cudaEventCreateWithFlags(&evA0, cudaEventDisableTiming);
        cudaEventCreateWithFlags(&evA1, cudaEventDisableTiming);
        cudaEventCreateWithFlags(&evM,  cudaEventDisableTiming);
        cudaEventCreateWithFlags(&evS0, cudaEventDisableTiming);
        cudaEventCreateWithFlags(&evS1, cudaEventDisableTiming);
        cudaDeviceGetAttribute(&n_sm, cudaDevAttrMultiProcessorCount, 0);
        s_init = true;
    }

    const int egrid = (E + 255) / 256;
    const __half* B0L2self = p_B0 + 256 * 128;            // layer2 n=0..127
    const __half* B1L2self = p_B1 + 256 * 128;
    const __half* B0L2msg  = p_B0 + 256 * 128 + 128 * 128; // layer2 n=128..255

    auto agg_grid = [](int nodes) { return (nodes + 7) / 8; };
    auto tiles = [](int rows) { return (rows + 127) / 128; };
    auto pgrid = [&](int nt) { return nt < n_sm ? nt : n_sm; };

    // ---- fork: CSR build on s2; default: wprep -> xh -> gemm1 (launch #4) ----
    cudaEventRecord(evF, 0);
    cudaStreamWaitEvent(s2, evF, 0);
    zero_int_kernel<<<(N + 255) / 256, 256, 0, s2>>>(p_deg, N);          // #1
    wprep_kernel<<<(2 * 256 * 128 + 255) / 256, 256>>>(W_in, W_out);     // #2
    xh_kernel<<<(N * 32 + 255) / 256, 256>>>(x, N * 32);                 // #3
    {
        int nt = tiles(N);
        mma_gemm_kernel<<<pgrid(nt), GT, SMEM_TOTAL_GEMM>>>(             // #4
            p_xh, p_B0, p_B1, p_self, p_msg, N, nt);
    }
    deg_kernel<<<egrid, 256, 0, s2>>>(dst, E);
    scan_kernel<<<1, 1024, 0, s2>>>(N);
    fill_kernel<<<egrid, 256, 0, s2>>>(src, dst, E);
    cudaEventRecord(evJ, s2);

    // ---- agg1 chunks (default): h = relu(self1 + mean(msg1)) -> fp16 hh ----
    cudaStreamWaitEvent(0, evJ, 0);
    agg_csr_kernel<<<agg_grid(Nh), 128>>>(p_msg, p_self, nullptr, p_hh, 0, Nh, 1);
    cudaEventRecord(evA0, 0);
    agg_csr_kernel<<<agg_grid(N - Nh), 128>>>(p_msg, p_self, nullptr, p_hh, Nh, N, 1);
    cudaEventRecord(evA1, 0);

    // ---- layer-2 GEMM halves on s2, row-chunked behind agg1 chunks ----
    // chunk 0 (rows 0..Nh): both halves depend only on agg1 chunk 0
    cudaStreamWaitEvent(s2, evA0, 0);
    {
        int nt = tiles(Nh);
        mma_gemm_n128_kernel<<<pgrid(nt), GT, SMEM_TOTAL_N128, s2>>>(
            p_hh, B0L2msg, nullptr, p_msg2, 0, N, nt);
        mma_gemm_n128_kernel<<<pgrid(nt), GT, SMEM_TOTAL_N128, s2>>>(
            p_hh, B0L2self, B1L2self, p_self2h, 0, N, nt);
        cudaEventRecord(evS0, s2);
    }
    // chunk 1 (rows Nh..N)
    cudaStreamWaitEvent(s2, evA1, 0);
    {
        int nt = tiles(N - Nh);
        mma_gemm_n128_kernel<<<pgrid(nt), GT, SMEM_TOTAL_N128, s2>>>(
            p_hh, B0L2msg, nullptr, p_msg2, Nh, N, nt);
        cudaEventRecord(evM, s2);                 // msg2 fully ready
        mma_gemm_n128_kernel<<<pgrid(nt), GT, SMEM_TOTAL_N128, s2>>>(
            p_hh, B0L2self, B1L2self, p_self2h, Nh, N, nt);
        cudaEventRecord(evS1, s2);
    }

    // ---- agg2 chunks (default): out = self2 + mean(msg2) ----
    // chunk i gathers ALL msg2 (evM) but reads only self2 rows of chunk i.
    cudaStreamWaitEvent(0, evM, 0);
    cudaStreamWaitEvent(0, evS0, 0);
    agg_csr_kernel<<<agg_grid(Nh), 128>>>(p_msg2, p_self2h, out, nullptr, 0, Nh, 0);
    cudaStreamWaitEvent(0, evS1, 0);
    agg_csr_kernel<<<agg_grid(N - Nh), 128>>>(p_msg2, p_self2h, out, nullptr, Nh, N, 0);
}